// round 3
// baseline (speedup 1.0000x reference)
#include <cuda_runtime.h>
#include <math.h>

#define H 1536
#define HK 8
#define HV 16
#define DK 64
#define DV 64
#define KEY_DIM 512
#define VALUE_DIM 1024
#define CONV_DIM 2048
#define NROWS_A (CONV_DIM + VALUE_DIM + 2*HV)   // 3104

__device__ __align__(16) float g_qkv[CONV_DIM];
__device__ __align__(16) float g_z[VALUE_DIM];
__device__ __align__(16) float g_ab[2*HV];
__device__ __align__(16) float g_outf[VALUE_DIM];

__device__ __forceinline__ float warp_sum(float v) {
#pragma unroll
    for (int o = 16; o > 0; o >>= 1) v += __shfl_xor_sync(0xffffffffu, v, o);
    return v;
}

// ---------------- Kernel A: fused input GEMVs (qkv, z, a, b) -----------------
// 3104 rows x 1536 cols. One warp per row, 8 rows per 256-thread block.
__global__ __launch_bounds__(256) void gemv_in(
    const float* __restrict__ x,
    const float* __restrict__ Wqkv, const float* __restrict__ Wz,
    const float* __restrict__ Wa,   const float* __restrict__ Wb)
{
    __shared__ __align__(16) float sx[H];
    const int tid = threadIdx.x;
    const float4* x4 = (const float4*)x;
#pragma unroll
    for (int i = tid; i < H / 4; i += 256) ((float4*)sx)[i] = x4[i];
    __syncthreads();

    const int row  = blockIdx.x * 8 + (tid >> 5);
    const int lane = tid & 31;

    const float* w;
    float* dst;
    if (row < CONV_DIM) {
        w = Wqkv + (size_t)row * H;            dst = &g_qkv[row];
    } else if (row < CONV_DIM + VALUE_DIM) {
        int r = row - CONV_DIM;
        w = Wz + (size_t)r * H;                dst = &g_z[r];
    } else if (row < CONV_DIM + VALUE_DIM + HV) {
        int r = row - CONV_DIM - VALUE_DIM;
        w = Wa + (size_t)r * H;                dst = &g_ab[r];
    } else {
        int r = row - CONV_DIM - VALUE_DIM - HV;
        w = Wb + (size_t)r * H;                dst = &g_ab[HV + r];
    }

    const float4* w4 = (const float4*)w;
    const float4* s4 = (const float4*)sx;
    float acc = 0.f;
#pragma unroll
    for (int j = 0; j < H / 128; ++j) {        // 12 iterations of float4
        float4 a = w4[lane + j * 32];
        float4 b = s4[lane + j * 32];
        acc += a.x * b.x + a.y * b.y + a.z * b.z + a.w * b.w;
    }
    acc = warp_sum(acc);
    if (lane == 0) *dst = acc;
}

// ------------- Kernel B: conv + l2norm + delta rule + gated RMSNorm ----------
// One block per value head. new_state is never materialized:
//   out[v] = e^g * (S^T q)[v] + (q.k) * beta * (v[v] - e^g * (S^T k)[v])
__global__ __launch_bounds__(256) void delta_kernel(
    const float* __restrict__ convw, const float* __restrict__ Alog,
    const float* __restrict__ dtb,   const float* __restrict__ nw,
    const float* __restrict__ state, const float* __restrict__ cache)
{
    const int h   = blockIdx.x;       // value head 0..15
    const int kh  = h >> 1;           // key head (repeat factor 2)
    const int tid = threadIdx.x;
    const int lane = tid & 31, wid = tid >> 5;

    __shared__ float sq[DK], sk[DK], sv[DV];
    __shared__ float s_qs, s_ks, s_qk, s_eg, s_beta, s_rms;
    __shared__ float r_part[256], o_part[256];

    // Per-channel causal conv (K=4 taps) + SiLU for the 192 channels this head needs.
    if (tid < 192) {
        int ch;
        if (tid < 64)       ch = kh * 64 + tid;                      // q channel
        else if (tid < 128) ch = KEY_DIM + kh * 64 + (tid - 64);     // k channel
        else                ch = 2 * KEY_DIM + h * 64 + (tid - 128); // v channel
        float co = g_qkv[ch]        * convw[ch * 4 + 3]
                 + cache[ch * 3 + 0] * convw[ch * 4 + 0]
                 + cache[ch * 3 + 1] * convw[ch * 4 + 1]
                 + cache[ch * 3 + 2] * convw[ch * 4 + 2];
        co = co / (1.f + expf(-co));  // silu
        if (tid < 64)       sq[tid] = co;
        else if (tid < 128) sk[tid - 64] = co;
        else                sv[tid - 128] = co;
    }
    __syncthreads();

    // Warp-parallel reductions: |q|^2, |k|^2, q.k (raw), plus scalar gates.
    if (wid == 0) {
        float a = sq[lane], b = sq[lane + 32];
        float s = warp_sum(a * a + b * b);
        if (lane == 0) s_qs = rsqrtf(s + 1e-12f) * 0.125f;  // * Dk^-0.5
    } else if (wid == 1) {
        float a = sk[lane], b = sk[lane + 32];
        float s = warp_sum(a * a + b * b);
        if (lane == 0) s_ks = rsqrtf(s + 1e-12f);
    } else if (wid == 2) {
        float s = warp_sum(sq[lane] * sk[lane] + sq[lane + 32] * sk[lane + 32]);
        if (lane == 0) s_qk = s;
    } else if (wid == 3 && lane == 0) {
        float aa = g_ab[h] + dtb[h];
        float sp = (aa > 20.f) ? aa : log1pf(expf(aa));      // softplus
        s_eg = expf(-expf(Alog[h]) * sp);                    // exp(g)
        float br = g_ab[HV + h];
        s_beta = 1.f / (1.f + expf(-br));                    // sigmoid
    }
    __syncthreads();

    const float qk = s_qk * s_qs * s_ks;

    // Normalize q, k in place.
    if (tid < 64)       sq[tid]      *= s_qs;
    else if (tid < 128) sk[tid - 64] *= s_ks;
    __syncthreads();

    // S^T q and S^T k: 4 k-quarters per v column (256 threads = 4 x 64).
    const int v  = tid & 63;
    const int kq = tid >> 6;
    const float* st = state + (size_t)h * DK * DV;
    float ar = 0.f, ao = 0.f;
#pragma unroll
    for (int kk = 0; kk < 16; ++kk) {
        int k = kq * 16 + kk;
        float s = st[k * DV + v];
        ar += s * sk[k];
        ao += s * sq[k];
    }
    r_part[tid] = ar; o_part[tid] = ao;
    __syncthreads();

    if (tid < 64) {
        float r0 = r_part[v] + r_part[64 + v] + r_part[128 + v] + r_part[192 + v];
        float o0 = o_part[v] + o_part[64 + v] + o_part[128 + v] + o_part[192 + v];
        float delta = (sv[v] - s_eg * r0) * s_beta;
        float out   = s_eg * o0 + qk * delta;
        r_part[v] = out * out;   // reuse for RMS reduction
        o_part[v] = out;
    }
    __syncthreads();
    if (wid == 0) {
        float s = warp_sum(r_part[lane] + r_part[lane + 32]);
        if (lane == 0) s_rms = rsqrtf(s * (1.f / 64.f) + 1e-6f);
    }
    __syncthreads();
    if (tid < 64) {
        float zg  = g_z[h * 64 + v];
        float sil = zg / (1.f + expf(-zg));
        g_outf[h * 64 + v] = nw[v] * o_part[v] * s_rms * sil;
    }
}

// ---------------- Kernel C: y = W_out @ out_final ----------------------------
__global__ __launch_bounds__(256) void gemv_out(
    const float* __restrict__ Wout, float* __restrict__ y)
{
    __shared__ __align__(16) float so[VALUE_DIM];
    const int tid = threadIdx.x;
#pragma unroll
    for (int i = tid; i < VALUE_DIM / 4; i += 256)
        ((float4*)so)[i] = ((const float4*)g_outf)[i];
    __syncthreads();

    const int row  = blockIdx.x * 8 + (tid >> 5);
    const int lane = tid & 31;
    const float4* w4 = (const float4*)(Wout + (size_t)row * VALUE_DIM);
    const float4* s4 = (const float4*)so;
    float acc = 0.f;
#pragma unroll
    for (int j = 0; j < VALUE_DIM / 128; ++j) {   // 8 iterations
        float4 a = w4[lane + j * 32];
        float4 b = s4[lane + j * 32];
        acc += a.x * b.x + a.y * b.y + a.z * b.z + a.w * b.w;
    }
    acc = warp_sum(acc);
    if (lane == 0) y[row] = acc;
}

extern "C" void kernel_launch(void* const* d_in, const int* in_sizes, int n_in,
                              void* d_out, int out_size)
{
    const float* x     = (const float*)d_in[0];   // hidden_states [1536]
    const float* Wqkv  = (const float*)d_in[1];   // [2048,1536]
    const float* Wz    = (const float*)d_in[2];   // [1024,1536]
    const float* Wa    = (const float*)d_in[3];   // [16,1536]
    const float* Wb    = (const float*)d_in[4];   // [16,1536]
    const float* Wout  = (const float*)d_in[5];   // [1536,1024]
    const float* convw = (const float*)d_in[6];   // [2048,4]
    const float* Alog  = (const float*)d_in[7];   // [16]
    const float* dtb   = (const float*)d_in[8];   // [16]
    const float* nw    = (const float*)d_in[9];   // [64]
    const float* state = (const float*)d_in[10];  // [16,64,64]
    const float* cache = (const float*)d_in[11];  // [2048,3]
    float* y = (float*)d_out;                     // [1536]

    gemv_in<<<NROWS_A / 8, 256>>>(x, Wqkv, Wz, Wa, Wb);
    delta_kernel<<<HV, 256>>>(convw, Alog, dtb, nw, state, cache);
    gemv_out<<<H / 8, 256>>>(Wout, y);
}